// round 16
// baseline (speedup 1.0000x reference)
#include <cuda_runtime.h>
#include <cuda_bf16.h>
#include <cstdint>

#define T_STEPS 800
#define UNITS   1024
#define BATCH   32
#define NFEAT   161
#define GRID    128
#define TPM     256
#define CLIPV   20.0f

#define CK 16
#define CN 8
#define KC 64
#define NC 128
#define QNAN_U 0x7fc00000u

// SMEM: bf16 tiles, 144B pitch (ldmatrix conflict-free)
#define PITCHB   144
#define OFF_U1   0            // U hi: 128 x 144B
#define OFF_U2   18432
#define OFF_H1   36864        // h hi: 64 x 144B
#define OFF_H2   46080
#define OFF_SCR  55296        // epilogue scratch [64][8]
#define SMEM_BYTES 57360

__device__ float    g_xw[T_STEPS][BATCH][UNITS];
__device__ float    g_part[3][CK][64][UNITS];     // [buf][kchunk][n][col]
__device__ float    g_hrep[3][CK][CN][64][KC];    // per-consumer h replicas
__device__ unsigned g_P[CN];
__device__ unsigned g_X;

typedef unsigned long long ull;

__device__ __forceinline__ void fma2(ull& d, ull a, ull b) {
    asm("fma.rn.f32x2 %0, %1, %2, %0;" : "+l"(d) : "l"(a), "l"(b));
}
__device__ __forceinline__ ull pack2(float v) {
    ull r; asm("mov.b64 %0, {%1, %1};" : "=l"(r) : "f"(v)); return r;
}
__device__ __forceinline__ float2 unpack2(ull v) {
    float2 r; asm("mov.b64 {%0, %1}, %2;" : "=f"(r.x), "=f"(r.y) : "l"(v)); return r;
}
__device__ __forceinline__ void ctr_arrive(unsigned* c) {
    __syncthreads();
    if (threadIdx.x == 0)
        asm volatile("red.release.gpu.global.add.u32 [%0], %1;"
                     :: "l"(c), "r"(1u) : "memory");
}
__device__ __forceinline__ void ctr_wait(unsigned* c, unsigned target) {
    if (threadIdx.x == 0) {
        unsigned v;
        do {
            asm volatile("ld.acquire.gpu.global.u32 %0, [%1];"
                         : "=r"(v) : "l"(c) : "memory");
        } while (v < target);
    }
    __syncthreads();
}
__device__ __forceinline__ uint32_t smem_u32(const void* p) {
    uint32_t a;
    asm("{ .reg .u64 t; cvta.to.shared.u64 t, %1; cvt.u32.u64 %0, t; }" : "=r"(a) : "l"(p));
    return a;
}
__device__ __forceinline__ uint32_t cvtpack(float hi, float lo) {
    uint32_t w;
    asm("cvt.rn.satfinite.bf16x2.f32 %0, %1, %2;" : "=r"(w) : "f"(hi), "f"(lo));
    return w;
}
__device__ __forceinline__ float bflo(uint32_t w) { return __uint_as_float(w << 16); }
__device__ __forceinline__ float bfhi(uint32_t w) { return __uint_as_float(w & 0xffff0000u); }
__device__ __forceinline__ float2 ldcg2(const float* p) {
    return __ldcg(reinterpret_cast<const float2*>(p));
}
__device__ __forceinline__ void ldsm4(uint32_t* r, uint32_t addr) {
    asm volatile("ldmatrix.sync.aligned.m8n8.x4.shared.b16 {%0,%1,%2,%3}, [%4];"
                 : "=r"(r[0]), "=r"(r[1]), "=r"(r[2]), "=r"(r[3]) : "r"(addr));
}
__device__ __forceinline__ void mma16816(float* d, const uint32_t* a, const uint32_t* b) {
    asm volatile("mma.sync.aligned.m16n8k16.row.col.f32.bf16.bf16.f32 "
                 "{%0,%1,%2,%3}, {%4,%5,%6,%7}, {%8,%9}, {%0,%1,%2,%3};"
                 : "+f"(d[0]), "+f"(d[1]), "+f"(d[2]), "+f"(d[3])
                 : "r"(a[0]), "r"(a[1]), "r"(a[2]), "r"(a[3]), "r"(b[0]), "r"(b[1]));
}
__device__ __forceinline__ float4 ld_rlx4(const float4* p) {
    float4 v;
    asm volatile("ld.relaxed.gpu.global.v4.f32 {%0,%1,%2,%3}, [%4];"
                 : "=f"(v.x), "=f"(v.y), "=f"(v.z), "=f"(v.w) : "l"(p) : "memory");
    return v;
}
__device__ __forceinline__ void st_rlx2(float* p, float2 v) {
    asm volatile("st.relaxed.gpu.global.v2.f32 [%0], {%1,%2};"
                 :: "l"(p), "f"(v.x), "f"(v.y) : "memory");
}
__device__ __forceinline__ void fence_ar() {
    asm volatile("fence.acq_rel.gpu;" ::: "memory");
}
__device__ __forceinline__ bool nan4(float4 v) {
    unsigned a = (__float_as_uint(v.x) & 0x7fffffffu) > 0x7f800000u;
    unsigned b = (__float_as_uint(v.y) & 0x7fffffffu) > 0x7f800000u;
    unsigned c = (__float_as_uint(v.z) & 0x7fffffffu) > 0x7f800000u;
    unsigned d = (__float_as_uint(v.w) & 0x7fffffffu) > 0x7f800000u;
    return (a | b | c | d) != 0u;
}

// ---------------------------------------------------------------------------
// init: replica buf0 = 0 (h_{-1}), bufs 1,2 = NaN; counters = 0.
// ---------------------------------------------------------------------------
__global__ void init_kernel() {
    const int NB = CK * CN * 64 * KC;
    const float qn = __uint_as_float(QNAN_U);
    int i = blockIdx.x * blockDim.x + threadIdx.x;
    int stride = gridDim.x * blockDim.x;
    float* h = (float*)g_hrep;
    for (int j = i; j < NB; j += stride) {
        h[j] = 0.0f; h[NB + j] = qn; h[2 * NB + j] = qn;
    }
    if (i < CN) g_P[i] = 0u;
    if (i == CN) g_X = 0u;
}

// ---------------------------------------------------------------------------
// Persistent kernel: xw phase -> global barrier -> bidirectional scan.
// Scan: per CTA (kc,nc) HMMA split-bf16 partial GEMM; P counter for partials;
// h exchange via per-consumer replicas with NaN-sentinel poll (no C counter).
// ---------------------------------------------------------------------------
__global__ void __launch_bounds__(TPM, 1) main_kernel(
    const float* __restrict__ inp,  const float* __restrict__ W,
    const float* __restrict__ Uw,   const float* __restrict__ bias,
    float* __restrict__ out) {
    extern __shared__ __align__(16) char sm[];
    const uint32_t sb = smem_u32(sm);
    float* scr = reinterpret_cast<float*>(sm + OFF_SCR);

    const int tid = threadIdx.x, wid = tid >> 5, lane = tid & 31;
    const int bid = blockIdx.x;
    const int kc = bid >> 3, nc = bid & 7;
    const int k0g = kc * KC, c0 = nc * NC;

    // ================= xw phase: xw[t][b][u], 50 (t,utile) tasks =================
    {
        float* in_s = reinterpret_cast<float*>(sm);   // 23.2KB, aliases U region
        const int cq = tid & 31, bq = tid >> 5;
        const int b0 = bq * 4;
        for (int i = 0; i < 50; i++) {
            int task = bid * 50 + i;
            int t = task >> 3, u0 = (task & 7) * 128;
            int uu = u0 + cq * 4;
            __syncthreads();
            for (int idx = tid; idx < BATCH * NFEAT; idx += TPM) {
                int b = idx / NFEAT, f = idx - b * NFEAT;
                in_s[f * 36 + b] = inp[(b * T_STEPS + t) * NFEAT + f];
            }
            __syncthreads();

            ull acc[4][2];
            #pragma unroll
            for (int j = 0; j < 4; j++) { acc[j][0] = 0ull; acc[j][1] = 0ull; }
            const float4* Wp = reinterpret_cast<const float4*>(W) + (uu >> 2);
            #pragma unroll 1
            for (int f = 0; f < NFEAT; f++) {
                ulonglong2 ip = *reinterpret_cast<const ulonglong2*>(&in_s[f * 36 + b0]);
                float4 w4 = __ldg(Wp + f * (UNITS / 4));
                ull s0 = pack2(w4.x), s1 = pack2(w4.y), s2 = pack2(w4.z), s3 = pack2(w4.w);
                fma2(acc[0][0], ip.x, s0); fma2(acc[0][1], ip.y, s0);
                fma2(acc[1][0], ip.x, s1); fma2(acc[1][1], ip.y, s1);
                fma2(acc[2][0], ip.x, s2); fma2(acc[2][1], ip.y, s2);
                fma2(acc[3][0], ip.x, s3); fma2(acc[3][1], ip.y, s3);
            }
            float4 bv = *reinterpret_cast<const float4*>(bias + uu);
            float2 a0[4], a1[4];
            #pragma unroll
            for (int j = 0; j < 4; j++) { a0[j] = unpack2(acc[j][0]); a1[j] = unpack2(acc[j][1]); }
            *reinterpret_cast<float4*>(&g_xw[t][b0 + 0][uu]) =
                make_float4(a0[0].x + bv.x, a0[1].x + bv.y, a0[2].x + bv.z, a0[3].x + bv.w);
            *reinterpret_cast<float4*>(&g_xw[t][b0 + 1][uu]) =
                make_float4(a0[0].y + bv.x, a0[1].y + bv.y, a0[2].y + bv.z, a0[3].y + bv.w);
            *reinterpret_cast<float4*>(&g_xw[t][b0 + 2][uu]) =
                make_float4(a1[0].x + bv.x, a1[1].x + bv.y, a1[2].x + bv.z, a1[3].x + bv.w);
            *reinterpret_cast<float4*>(&g_xw[t][b0 + 3][uu]) =
                make_float4(a1[0].y + bv.x, a1[1].y + bv.y, a1[2].y + bv.z, a1[3].y + bv.w);
        }
    }
    ctr_arrive(&g_X);
    ctr_wait(&g_X, GRID);

    // ================= scan prologue =================
    // U tiles: U1/U2[col][k] bf16 hi/lo, pitch 144B
    for (int idx = tid; idx < NC * KC; idx += TPM) {
        int m = idx & 127, k = idx >> 7;
        float u = __ldg(Uw + (k0g + k) * UNITS + c0 + m);
        __nv_bfloat16 u1 = __float2bfloat16(u);
        __nv_bfloat16 u2 = __float2bfloat16(u - __bfloat162float(u1));
        *reinterpret_cast<__nv_bfloat16*>(sm + OFF_U1 + m * PITCHB + k * 2) = u1;
        *reinterpret_cast<__nv_bfloat16*>(sm + OFF_U2 + m * PITCHB + k * 2) = u2;
    }
    __syncthreads();

    // identities
    const int pn = tid >> 2, q4 = tid & 3;            // poll/convert: row, k-quarter
    const int n_r = tid >> 2, u2i = (tid & 3) * 2;    // reduce: row, unit pair
    const int rdir = n_r >> 5, rb = n_r & 31;
    const int ru2 = k0g + nc * 8 + u2i;
    const int q = lane >> 3, rr = lane & 7;
    const uint32_t aoff = (uint32_t)((((q & 1) * 8 + rr) * PITCHB) + (q >> 1) * 16);
    const int c_base = wid * 16;
    const uint32_t boff = (uint32_t)(((c_base + (q >> 1) * 8 + rr) * PITCHB) + (q & 1) * 16);
    const float4 qn4 = make_float4(__uint_as_float(QNAN_U), __uint_as_float(QNAN_U),
                                   __uint_as_float(QNAN_U), __uint_as_float(QNAN_U));
    float2 hn;

    #pragma unroll 1
    for (int t = 0; t < T_STEPS; t++) {
        const int pb = t % 3, hb3 = (t + 1) % 3;

        // ---- poll own replica (= C-wait + stage), convert to split bf16 ----
        {
            const float4* hs = reinterpret_cast<const float4*>(
                                   &g_hrep[pb][kc][nc][pn][q4 * 16]);
            float4 hv[4];
            #pragma unroll
            for (int i = 0; i < 4; i++) hv[i] = ld_rlx4(hs + i);
            for (;;) {
                unsigned bad = 0;
                #pragma unroll
                for (int i = 0; i < 4; i++)
                    if (nan4(hv[i])) { bad = 1; hv[i] = ld_rlx4(hs + i); }
                if (!bad) break;
            }
            fence_ar();   // acquire: pairs with reducers' release fences
            #pragma unroll
            for (int i = 0; i < 4; i++)
                __stcg(const_cast<float4*>(hs) + i, qn4);   // reset (private)

            uint32_t sbyte = (uint32_t)(pn * PITCHB + q4 * 32);
            #pragma unroll
            for (int h2 = 0; h2 < 2; h2++) {
                float4 a = hv[2 * h2], b4 = hv[2 * h2 + 1];
                uint32_t w0 = cvtpack(a.y, a.x),   w1 = cvtpack(a.w, a.z);
                uint32_t w2 = cvtpack(b4.y, b4.x), w3 = cvtpack(b4.w, b4.z);
                asm volatile("st.shared.v4.b32 [%0], {%1,%2,%3,%4};"
                             :: "r"(sb + OFF_H1 + sbyte + h2 * 16),
                                "r"(w0), "r"(w1), "r"(w2), "r"(w3) : "memory");
                uint32_t v0 = cvtpack(a.y - bfhi(w0),   a.x - bflo(w0));
                uint32_t v1 = cvtpack(a.w - bfhi(w1),   a.z - bflo(w1));
                uint32_t v2 = cvtpack(b4.y - bfhi(w2),  b4.x - bflo(w2));
                uint32_t v3 = cvtpack(b4.w - bfhi(w3),  b4.z - bflo(w3));
                asm volatile("st.shared.v4.b32 [%0], {%1,%2,%3,%4};"
                             :: "r"(sb + OFF_H2 + sbyte + h2 * 16),
                                "r"(v0), "r"(v1), "r"(v2), "r"(v3) : "memory");
            }
        }
        __syncthreads();

        // ---- GEMM: U1h1 + U1h2 + U2h1; warp owns 16 cols ----
        float d[4][2][4];
        #pragma unroll
        for (int mt = 0; mt < 4; mt++)
            #pragma unroll
            for (int nt = 0; nt < 2; nt++)
                #pragma unroll
                for (int i = 0; i < 4; i++) d[mt][nt][i] = 0.0f;

        #pragma unroll
        for (int ks = 0; ks < 4; ks++) {
            const uint32_t kb = (uint32_t)(ks * 32);
            uint32_t ah1[4][4], ah2[4][4], bu1[4], bu2[4];
            #pragma unroll
            for (int mt = 0; mt < 4; mt++)
                ldsm4(ah1[mt], sb + OFF_H1 + aoff + mt * (16 * PITCHB) + kb);
            ldsm4(bu1, sb + OFF_U1 + boff + kb);
            #pragma unroll
            for (int mt = 0; mt < 4; mt++)
                #pragma unroll
                for (int nt = 0; nt < 2; nt++)
                    mma16816(d[mt][nt], ah1[mt], &bu1[nt * 2]);
            ldsm4(bu2, sb + OFF_U2 + boff + kb);
            #pragma unroll
            for (int mt = 0; mt < 4; mt++)
                #pragma unroll
                for (int nt = 0; nt < 2; nt++)
                    mma16816(d[mt][nt], ah1[mt], &bu2[nt * 2]);
            #pragma unroll
            for (int mt = 0; mt < 4; mt++)
                ldsm4(ah2[mt], sb + OFF_H2 + aoff + mt * (16 * PITCHB) + kb);
            #pragma unroll
            for (int mt = 0; mt < 4; mt++)
                #pragma unroll
                for (int nt = 0; nt < 2; nt++)
                    mma16816(d[mt][nt], ah2[mt], &bu1[nt * 2]);
        }

        // ---- store partials ----
        {
            float* gp = &g_part[pb][kc][0][0];
            const int urow = c0 + c_base + (lane & 3) * 2;
            const int nrow = lane >> 2;
            #pragma unroll
            for (int mt = 0; mt < 4; mt++)
                #pragma unroll
                for (int nt = 0; nt < 2; nt++) {
                    int u = urow + nt * 8;
                    int r0 = mt * 16 + nrow;
                    __stcg(reinterpret_cast<float2*>(gp + r0 * UNITS + u),
                           make_float2(d[mt][nt][0], d[mt][nt][1]));
                    __stcg(reinterpret_cast<float2*>(gp + (r0 + 8) * UNITS + u),
                           make_float2(d[mt][nt][2], d[mt][nt][3]));
                }
        }
        ctr_arrive(&g_P[nc]);

        // prefetch x for the reduce
        int xt = rdir ? (T_STEPS - 1 - t) : t;
        float2 xv = ldcg2(&g_xw[xt][rb][ru2]);

        // ---- wait producers, reduce own slice, publish to 8 replicas ----
        ctr_wait(&g_P[kc >> 1], 16u * (unsigned)(t + 1));
        {
            float2 s = xv;
            #pragma unroll
            for (int j = 0; j < CK; j++) {
                float2 p = ldcg2(&g_part[pb][j][n_r][ru2]);
                s.x += p.x; s.y += p.y;
            }
            hn.x = fminf(fmaxf(s.x, 0.f), CLIPV);
            hn.y = fminf(fmaxf(s.y, 0.f), CLIPV);
        }
        fence_ar();   // release: resets + partial reads before replica stores
        #pragma unroll
        for (int c = 0; c < CN; c++)
            st_rlx2(&g_hrep[hb3][kc][c][n_r][nc * 8 + u2i], hn);
    }

    // ---- epilogue: out[b][u] = hf + hb for this CTA's 8-unit slice ----
    scr[n_r * 8 + u2i]     = hn.x;
    scr[n_r * 8 + u2i + 1] = hn.y;
    __syncthreads();
    {
        int b = tid >> 3, uo = tid & 7;
        out[b * UNITS + k0g + nc * 8 + uo] = scr[b * 8 + uo] + scr[(b + 32) * 8 + uo];
    }
}

// ---------------------------------------------------------------------------
extern "C" void kernel_launch(void* const* d_in, const int* in_sizes, int n_in,
                              void* d_out, int out_size) {
    const float* inp  = (const float*)d_in[0];  // [32, 800, 161]
    const float* W    = (const float*)d_in[1];  // [161, 1024]
    const float* Uw   = (const float*)d_in[2];  // [1024, 1024]
    const float* bias = (const float*)d_in[3];  // [1024]
    float* out        = (float*)d_out;          // [32, 1024]

    cudaFuncSetAttribute(main_kernel, cudaFuncAttributeMaxDynamicSharedMemorySize,
                         SMEM_BYTES);

    init_kernel<<<64, TPM>>>();
    main_kernel<<<GRID, TPM, SMEM_BYTES>>>(inp, W, Uw, bias, out);
}

// round 17
// speedup vs baseline: 1.5920x; 1.5920x over previous
#include <cuda_runtime.h>
#include <cuda_bf16.h>
#include <cstdint>

#define T_STEPS 800
#define UNITS   1024
#define BATCH   32
#define NFEAT   161
#define GRID    128
#define TPB     256
#define TPM     256
#define CLIPV   20.0f

#define CK 16
#define CN 8
#define KC 64
#define NC 128

// SMEM: bf16 tiles, 144B pitch (ldmatrix conflict-free)
#define PITCHB   144
#define OFF_U1   0            // U hi: 128 x 144B
#define OFF_U2   18432
#define OFF_H1   36864        // h hi: 64 x 144B
#define OFF_H2   46080
#define OFF_SCR  55296        // epilogue scratch [64][8]
#define SMEM_BYTES 57360

__device__ float    g_xw[T_STEPS][BATCH][UNITS];
__device__ float    g_part[3][CK][64][UNITS];   // [buf][kchunk][n=dir*32+b][col]
__device__ float    g_h[3][64][UNITS];          // [buf][n][u]
__device__ unsigned g_P[CN];
__device__ unsigned g_C[CK];

typedef unsigned long long ull;

__device__ __forceinline__ void fma2(ull& d, ull a, ull b) {
    asm("fma.rn.f32x2 %0, %1, %2, %0;" : "+l"(d) : "l"(a), "l"(b));
}
__device__ __forceinline__ ull pack2(float v) {
    ull r; asm("mov.b64 %0, {%1, %1};" : "=l"(r) : "f"(v)); return r;
}
__device__ __forceinline__ float2 unpack2(ull v) {
    float2 r; asm("mov.b64 {%0, %1}, %2;" : "=f"(r.x), "=f"(r.y) : "l"(v)); return r;
}
__device__ __forceinline__ void ctr_arrive(unsigned* c) {
    __syncthreads();
    if (threadIdx.x == 0)
        asm volatile("red.release.gpu.global.add.u32 [%0], %1;"
                     :: "l"(c), "r"(1u) : "memory");
}
__device__ __forceinline__ void ctr_wait(unsigned* c, unsigned target) {
    if (threadIdx.x == 0) {
        unsigned v;
        do {
            asm volatile("ld.acquire.gpu.global.u32 %0, [%1];"
                         : "=r"(v) : "l"(c) : "memory");
        } while (v < target);
    }
    __syncthreads();
}
__device__ __forceinline__ uint32_t smem_u32(const void* p) {
    uint32_t a;
    asm("{ .reg .u64 t; cvta.to.shared.u64 t, %1; cvt.u32.u64 %0, t; }" : "=r"(a) : "l"(p));
    return a;
}
__device__ __forceinline__ uint32_t cvtpack(float hi, float lo) {
    uint32_t w;
    asm("cvt.rn.satfinite.bf16x2.f32 %0, %1, %2;" : "=r"(w) : "f"(hi), "f"(lo));
    return w;
}
__device__ __forceinline__ float bflo(uint32_t w) { return __uint_as_float(w << 16); }
__device__ __forceinline__ float bfhi(uint32_t w) { return __uint_as_float(w & 0xffff0000u); }
__device__ __forceinline__ float2 ldcg2(const float* p) {
    return __ldcg(reinterpret_cast<const float2*>(p));
}
__device__ __forceinline__ float4 ldcg4(const float* p) {
    return __ldcg(reinterpret_cast<const float4*>(p));
}
__device__ __forceinline__ void ldsm4(uint32_t* r, uint32_t addr) {
    asm volatile("ldmatrix.sync.aligned.m8n8.x4.shared.b16 {%0,%1,%2,%3}, [%4];"
                 : "=r"(r[0]), "=r"(r[1]), "=r"(r[2]), "=r"(r[3]) : "r"(addr));
}
__device__ __forceinline__ void mma16816(float* d, const uint32_t* a, const uint32_t* b) {
    asm volatile("mma.sync.aligned.m16n8k16.row.col.f32.bf16.bf16.f32 "
                 "{%0,%1,%2,%3}, {%4,%5,%6,%7}, {%8,%9}, {%0,%1,%2,%3};"
                 : "+f"(d[0]), "+f"(d[1]), "+f"(d[2]), "+f"(d[3])
                 : "r"(a[0]), "r"(a[1]), "r"(a[2]), "r"(a[3]), "r"(b[0]), "r"(b[1]));
}

// ---------------------------------------------------------------------------
__global__ void init_kernel() {
    int i = blockIdx.x * blockDim.x + threadIdx.x;
    int stride = gridDim.x * blockDim.x;
    for (int j = i; j < 64 * UNITS; j += stride) ((float*)g_h)[j] = 0.0f;  // buf 0
    if (i < CN) g_P[i] = 0u;
    if (i < CK) g_C[i] = 0u;
}

// ---------------------------------------------------------------------------
// xw[t][b][u] = sum_f inp[b][t][f] * W[f][u] + bias[u]   (u-contiguous)
// ---------------------------------------------------------------------------
__global__ void __launch_bounds__(TPB) xw_kernel(const float* __restrict__ inp,
                                                 const float* __restrict__ W,
                                                 const float* __restrict__ bias) {
    __shared__ __align__(16) float in_s[NFEAT * 36];
    const int t = blockIdx.y, u0 = blockIdx.x * 128, tid = threadIdx.x;
    const int cq = tid & 31, bq = tid >> 5;
    const int uu = u0 + cq * 4, b0 = bq * 4;

    for (int idx = tid; idx < BATCH * NFEAT; idx += TPB) {
        int b = idx / NFEAT, f = idx - b * NFEAT;
        in_s[f * 36 + b] = inp[(b * T_STEPS + t) * NFEAT + f];
    }
    __syncthreads();

    ull acc[4][2];
    #pragma unroll
    for (int i = 0; i < 4; i++) { acc[i][0] = 0ull; acc[i][1] = 0ull; }

    const float4* Wp = reinterpret_cast<const float4*>(W) + (uu >> 2);
    #pragma unroll 1
    for (int f = 0; f < NFEAT; f++) {
        ulonglong2 ip = *reinterpret_cast<const ulonglong2*>(&in_s[f * 36 + b0]);
        float4 w4 = __ldg(Wp + f * (UNITS / 4));
        ull s0 = pack2(w4.x), s1 = pack2(w4.y), s2 = pack2(w4.z), s3 = pack2(w4.w);
        fma2(acc[0][0], ip.x, s0); fma2(acc[0][1], ip.y, s0);
        fma2(acc[1][0], ip.x, s1); fma2(acc[1][1], ip.y, s1);
        fma2(acc[2][0], ip.x, s2); fma2(acc[2][1], ip.y, s2);
        fma2(acc[3][0], ip.x, s3); fma2(acc[3][1], ip.y, s3);
    }
    float4 bv = *reinterpret_cast<const float4*>(bias + uu);
    float2 a0[4], a1[4];
    #pragma unroll
    for (int i = 0; i < 4; i++) { a0[i] = unpack2(acc[i][0]); a1[i] = unpack2(acc[i][1]); }
    *reinterpret_cast<float4*>(&g_xw[t][b0 + 0][uu]) =
        make_float4(a0[0].x + bv.x, a0[1].x + bv.y, a0[2].x + bv.z, a0[3].x + bv.w);
    *reinterpret_cast<float4*>(&g_xw[t][b0 + 1][uu]) =
        make_float4(a0[0].y + bv.x, a0[1].y + bv.y, a0[2].y + bv.z, a0[3].y + bv.w);
    *reinterpret_cast<float4*>(&g_xw[t][b0 + 2][uu]) =
        make_float4(a1[0].x + bv.x, a1[1].x + bv.y, a1[2].x + bv.z, a1[3].x + bv.w);
    *reinterpret_cast<float4*>(&g_xw[t][b0 + 3][uu]) =
        make_float4(a1[0].y + bv.x, a1[1].y + bv.y, a1[2].y + bv.z, a1[3].y + bv.w);
}

// ---------------------------------------------------------------------------
// Persistent scan: HMMA split-bf16 GEMM per CTA (256 thr), P/C counters.
// ---------------------------------------------------------------------------
__global__ void __launch_bounds__(TPM, 1) rnn_kernel(const float* __restrict__ Uw,
                                                     float* __restrict__ out) {
    extern __shared__ __align__(16) char sm[];
    const uint32_t sb = smem_u32(sm);
    float* scr = reinterpret_cast<float*>(sm + OFF_SCR);

    const int tid = threadIdx.x, wid = tid >> 5, lane = tid & 31;
    const int bid = blockIdx.x;
    const int kc = bid >> 3, nc = bid & 7;
    const int k0g = kc * KC, c0 = nc * NC;

    // stage/convert identity: row pn (n = dir*32+b), k-quarter q4 (16 floats)
    const int pn = tid >> 2, q4 = tid & 3;
    // reduce identity: row n_r, unit pair u2i
    const int n_r = tid >> 2, u2i = (tid & 3) * 2;
    const int rdir = n_r >> 5, rb = n_r & 31;
    const int ru2 = k0g + nc * 8 + u2i;
    // ldmatrix addresses
    const int q = lane >> 3, rr = lane & 7;
    const uint32_t aoff = (uint32_t)((((q & 1) * 8 + rr) * PITCHB) + (q >> 1) * 16);
    const int c_base = wid * 16;
    const uint32_t boff = (uint32_t)(((c_base + (q >> 1) * 8 + rr) * PITCHB) + (q & 1) * 16);

    // ---- build U tiles once: U1/U2[col][k] bf16 hi/lo, pitch 144B ----
    for (int idx = tid; idx < NC * KC; idx += TPM) {
        int m = idx & 127, k = idx >> 7;
        float u = __ldg(Uw + (k0g + k) * UNITS + c0 + m);
        __nv_bfloat16 u1 = __float2bfloat16(u);
        __nv_bfloat16 u2 = __float2bfloat16(u - __bfloat162float(u1));
        *reinterpret_cast<__nv_bfloat16*>(sm + OFF_U1 + m * PITCHB + k * 2) = u1;
        *reinterpret_cast<__nv_bfloat16*>(sm + OFF_U2 + m * PITCHB + k * 2) = u2;
    }
    __syncthreads();

    float2 hn;

    #pragma unroll 1
    for (int t = 0; t < T_STEPS; t++) {
        const int pb = t % 3, hb = (t + 1) % 3;

        // ---- wait h_{t-1} ready, stage + split into H1/H2 ----
        ctr_wait(&g_C[kc], 8u * (unsigned)t);
        {
            const float* hsrc = &g_h[pb][pn][k0g + q4 * 16];
            float4 hv[4];
            #pragma unroll
            for (int i = 0; i < 4; i++) hv[i] = ldcg4(hsrc + i * 4);
            uint32_t sbyte = (uint32_t)(pn * PITCHB + q4 * 32);
            #pragma unroll
            for (int h2 = 0; h2 < 2; h2++) {
                float4 a = hv[2 * h2], b4 = hv[2 * h2 + 1];
                uint32_t w0 = cvtpack(a.y, a.x),   w1 = cvtpack(a.w, a.z);
                uint32_t w2 = cvtpack(b4.y, b4.x), w3 = cvtpack(b4.w, b4.z);
                asm volatile("st.shared.v4.b32 [%0], {%1,%2,%3,%4};"
                             :: "r"(sb + OFF_H1 + sbyte + h2 * 16),
                                "r"(w0), "r"(w1), "r"(w2), "r"(w3) : "memory");
                uint32_t v0 = cvtpack(a.y - bfhi(w0),   a.x - bflo(w0));
                uint32_t v1 = cvtpack(a.w - bfhi(w1),   a.z - bflo(w1));
                uint32_t v2 = cvtpack(b4.y - bfhi(w2),  b4.x - bflo(w2));
                uint32_t v3 = cvtpack(b4.w - bfhi(w3),  b4.z - bflo(w3));
                asm volatile("st.shared.v4.b32 [%0], {%1,%2,%3,%4};"
                             :: "r"(sb + OFF_H2 + sbyte + h2 * 16),
                                "r"(v0), "r"(v1), "r"(v2), "r"(v3) : "memory");
            }
        }
        __syncthreads();

        // ---- GEMM: U1h1 + U1h2 + U2h1; each warp owns 16 cols ----
        float d[4][2][4];
        #pragma unroll
        for (int mt = 0; mt < 4; mt++)
            #pragma unroll
            for (int nt = 0; nt < 2; nt++)
                #pragma unroll
                for (int i = 0; i < 4; i++) d[mt][nt][i] = 0.0f;

        #pragma unroll
        for (int ks = 0; ks < 4; ks++) {
            const uint32_t kb = (uint32_t)(ks * 32);
            uint32_t ah1[4][4], ah2[4][4], bu1[4], bu2[4];
            #pragma unroll
            for (int mt = 0; mt < 4; mt++)
                ldsm4(ah1[mt], sb + OFF_H1 + aoff + mt * (16 * PITCHB) + kb);
            ldsm4(bu1, sb + OFF_U1 + boff + kb);
            #pragma unroll
            for (int mt = 0; mt < 4; mt++)
                #pragma unroll
                for (int nt = 0; nt < 2; nt++)
                    mma16816(d[mt][nt], ah1[mt], &bu1[nt * 2]);
            ldsm4(bu2, sb + OFF_U2 + boff + kb);
            #pragma unroll
            for (int mt = 0; mt < 4; mt++)
                #pragma unroll
                for (int nt = 0; nt < 2; nt++)
                    mma16816(d[mt][nt], ah1[mt], &bu2[nt * 2]);
            #pragma unroll
            for (int mt = 0; mt < 4; mt++)
                ldsm4(ah2[mt], sb + OFF_H2 + aoff + mt * (16 * PITCHB) + kb);
            #pragma unroll
            for (int mt = 0; mt < 4; mt++)
                #pragma unroll
                for (int nt = 0; nt < 2; nt++)
                    mma16816(d[mt][nt], ah2[mt], &bu1[nt * 2]);
        }

        // ---- store partials: rows = n, cols consecutive u -> st.v2 ----
        {
            float* gp = &g_part[pb][kc][0][0];
            const int urow = c0 + c_base + (lane & 3) * 2;
            const int nrow = lane >> 2;
            #pragma unroll
            for (int mt = 0; mt < 4; mt++)
                #pragma unroll
                for (int nt = 0; nt < 2; nt++) {
                    int u = urow + nt * 8;
                    int r0 = mt * 16 + nrow;
                    __stcg(reinterpret_cast<float2*>(gp + r0 * UNITS + u),
                           make_float2(d[mt][nt][0], d[mt][nt][1]));
                    __stcg(reinterpret_cast<float2*>(gp + (r0 + 8) * UNITS + u),
                           make_float2(d[mt][nt][2], d[mt][nt][3]));
                }
        }
        ctr_arrive(&g_P[nc]);

        // prefetch x for the reduce
        int xt = rdir ? (T_STEPS - 1 - t) : t;
        float2 xv = ldcg2(&g_xw[xt][rb][ru2]);

        // ---- wait producers, reduce own slice -> g_h[hb] ----
        ctr_wait(&g_P[kc >> 1], 16u * (unsigned)(t + 1));
        {
            float2 s = xv;
            #pragma unroll
            for (int j = 0; j < CK; j++) {
                float2 p = ldcg2(&g_part[pb][j][n_r][ru2]);
                s.x += p.x; s.y += p.y;
            }
            hn.x = fminf(fmaxf(s.x, 0.f), CLIPV);
            hn.y = fminf(fmaxf(s.y, 0.f), CLIPV);
            __stcg(reinterpret_cast<float2*>(&g_h[hb][n_r][ru2]), hn);
        }
        ctr_arrive(&g_C[kc]);
    }

    // ---- epilogue: out[b][u] = hf + hb for this CTA's 8-unit slice ----
    scr[n_r * 8 + u2i]     = hn.x;
    scr[n_r * 8 + u2i + 1] = hn.y;
    __syncthreads();
    {
        int b = tid >> 3, uo = tid & 7;
        out[b * UNITS + k0g + nc * 8 + uo] = scr[b * 8 + uo] + scr[(b + 32) * 8 + uo];
    }
}

// ---------------------------------------------------------------------------
extern "C" void kernel_launch(void* const* d_in, const int* in_sizes, int n_in,
                              void* d_out, int out_size) {
    const float* inp  = (const float*)d_in[0];  // [32, 800, 161]
    const float* W    = (const float*)d_in[1];  // [161, 1024]
    const float* Uw   = (const float*)d_in[2];  // [1024, 1024]
    const float* bias = (const float*)d_in[3];  // [1024]
    float* out        = (float*)d_out;          // [32, 1024]

    cudaFuncSetAttribute(rnn_kernel, cudaFuncAttributeMaxDynamicSharedMemorySize,
                         SMEM_BYTES);

    init_kernel<<<64, TPB>>>();
    xw_kernel<<<dim3(8, T_STEPS, 1), TPB>>>(inp, W, bias);
    rnn_kernel<<<GRID, TPM, SMEM_BYTES>>>(Uw, out);
}